// round 1
// baseline (speedup 1.0000x reference)
#include <cuda_runtime.h>

#define BB 4
#define CC 64
#define HIN 96
#define WIN 96
#define HOUT 192
#define WOUT 192

// Scratch + parity-precomputed data (allocation-free rule: device globals)
__device__ float g_sta[BB*CC*HIN*WIN];   // sta_feat  [4,64,96,96]
__device__ float g_off[4][2];
__device__ float g_stoff[4][2];
__device__ float g_wcpx[4][512];         // [o*64+c]
__device__ float g_wepx[4][512];         // [c*8+o]

// ---------------------------------------------------------------------------
// K1: per-parity MLP -> offsets, st_offsets, routed expert matrices.
// Grid: 4 blocks (one per (ph,pw) combo), 256 threads.
// ---------------------------------------------------------------------------
__global__ void k1_parity(const float* __restrict__ b1w, const float* __restrict__ b1b,
                          const float* __restrict__ b2w, const float* __restrict__ b2b,
                          const float* __restrict__ rw,  const float* __restrict__ rb,
                          const float* __restrict__ ow,  const float* __restrict__ ob,
                          const float* __restrict__ sow, const float* __restrict__ sob,
                          const float* __restrict__ wc,  const float* __restrict__ we) {
  __shared__ float hid[64], emb[64], r[4];
  const int ci = blockIdx.x, tid = threadIdx.x;
  const float in2 = (ci >> 1) ? 0.25f : -0.25f;   // coor_h (row parity)
  const float in3 = (ci & 1)  ? 0.25f : -0.25f;   // coor_w (col parity)
  if (tid < 64) {
    float a = b1b[tid] + 0.5f*b1w[tid*4+0] + 0.5f*b1w[tid*4+1]
            + in2*b1w[tid*4+2] + in3*b1w[tid*4+3];
    hid[tid] = fmaxf(a, 0.f);
  }
  __syncthreads();
  if (tid < 64) {
    float a = b2b[tid];
    #pragma unroll 8
    for (int k = 0; k < 64; k++) a = fmaf(b2w[tid*64+k], hid[k], a);
    emb[tid] = fmaxf(a, 0.f);
  }
  __syncthreads();
  if (tid < 4) {
    float a = rb[tid];
    for (int k = 0; k < 64; k++) a = fmaf(rw[tid*64+k], emb[k], a);
    r[tid] = 1.f / (1.f + expf(-a));
  } else if (tid < 6) {
    int t = tid - 4; float a = ob[t];
    for (int k = 0; k < 64; k++) a = fmaf(ow[t*64+k], emb[k], a);
    g_off[ci][t] = a;
  } else if (tid < 8) {
    int t = tid - 6; float a = sob[t];
    for (int k = 0; k < 64; k++) a = fmaf(sow[t*64+k], emb[k], a);
    g_stoff[ci][t] = a;
  }
  __syncthreads();
  for (int e = tid; e < 512; e += 256) {
    float a = 0.f, bsum = 0.f;
    #pragma unroll
    for (int ex = 0; ex < 4; ex++) {
      a    = fmaf(r[ex], wc[ex*512+e], a);
      bsum = fmaf(r[ex], we[ex*512+e], bsum);
    }
    g_wcpx[ci][e] = a;
    g_wepx[ci][e] = bsum;
  }
}

// ---------------------------------------------------------------------------
// K2: fused  kernel_warp = lrelu(kc_w @ st_feat + kc_b)  +  25-tap sta conv.
// Block: 128 threads, one (batch b, row h, 32-px segment). All 64 channels.
// Thread tile: 4 channels x 4 pixels, k-vectorized float4 inner loop.
// smem: x halo tile, st_feat^T (swizzled), per-tap kc_w tile (swizzled), kc_b.
// ---------------------------------------------------------------------------
#define K2_SMEM_FLOATS (11520 + 2176 + 4352 + 1600)
__global__ __launch_bounds__(128) void k2_sta(const float* __restrict__ x,
                                              const float* __restrict__ st,
                                              const float* __restrict__ kcw,
                                              const float* __restrict__ kcb) {
  extern __shared__ float sm[];
  float* s_x  = sm;                  // [c][5][36]  11520
  float* s_st = sm + 11520;          // [px 0..31][68] swizzled k
  float* s_w  = s_st + 2176;         // [c 0..63][68] swizzled k
  float* s_kb = s_w + 4352;          // 1600

  const int b = blockIdx.z, h = blockIdx.y, w0 = blockIdx.x * 32;
  const int tid = threadIdx.x;

  // x halo tile: rows h-2..h+2 (clamped), cols w0-2..w0+33 (clamped)
  for (int e = tid; e < 64*5*36; e += 128) {
    int col = e % 36; int rr = (e / 36) % 5; int c = e / 180;
    int gy = min(max(h - 2 + rr, 0), HIN - 1);
    int gx = min(max(w0 - 2 + col, 0), WIN - 1);
    s_x[e] = x[((b*CC + c)*HIN + gy)*WIN + gx];
  }
  // st_feat^T tile with XOR swizzle on k-quads
  for (int e = tid; e < 2048; e += 128) {
    int px = e & 31; int k = e >> 5;
    float v = st[((b*CC + k)*HIN + h)*WIN + w0 + px];
    int sw = ((((k >> 2) ^ ((px >> 2) & 7)) << 2) | (k & 3));
    s_st[px*68 + sw] = v;
  }
  for (int e = tid; e < 1600; e += 128) s_kb[e] = kcb[e];

  const int pg = tid & 7, cg = tid >> 3;     // 8 pixel-groups, 16 channel-groups
  const int c0 = cg * 4, p0 = pg * 4;
  float acc[4][4] = {};

  for (int t = 0; t < 25; t++) {
    __syncthreads();   // previous tap's s_w reads done (also covers initial fills)
    // stage kc_w rows {c*25+t} transposed-read-friendly: s_w[c][k] swizzled
    for (int e4 = tid; e4 < 1024; e4 += 128) {
      int c = e4 >> 4; int k4 = e4 & 15;
      const float4 g = *(const float4*)&kcw[(c*25 + t)*64 + k4*4];
      int sw4 = ((k4 ^ ((c >> 2) & 7)) << 2);
      *(float4*)&s_w[c*68 + sw4] = g;
    }
    __syncthreads();

    float gacc[4][4];
    #pragma unroll
    for (int j = 0; j < 4; j++) {
      float bb = s_kb[(c0 + j)*25 + t];
      #pragma unroll
      for (int p = 0; p < 4; p++) gacc[j][p] = bb;
    }

    #pragma unroll 4
    for (int k4 = 0; k4 < 16; k4++) {
      const int ko = ((k4 ^ (cg & 7)) << 2);
      const int so = ((k4 ^ pg) << 2);
      float4 wv[4], sv[4];
      #pragma unroll
      for (int j = 0; j < 4; j++) wv[j] = *(const float4*)&s_w[(c0 + j)*68 + ko];
      #pragma unroll
      for (int p = 0; p < 4; p++) sv[p] = *(const float4*)&s_st[(p0 + p)*68 + so];
      #pragma unroll
      for (int j = 0; j < 4; j++)
        #pragma unroll
        for (int p = 0; p < 4; p++) {
          gacc[j][p] = fmaf(wv[j].x, sv[p].x, gacc[j][p]);
          gacc[j][p] = fmaf(wv[j].y, sv[p].y, gacc[j][p]);
          gacc[j][p] = fmaf(wv[j].z, sv[p].z, gacc[j][p]);
          gacc[j][p] = fmaf(wv[j].w, sv[p].w, gacc[j][p]);
        }
    }

    const int rr = t / 5, dw = t % 5;
    #pragma unroll
    for (int j = 0; j < 4; j++)
      #pragma unroll
      for (int p = 0; p < 4; p++) {
        float g = gacc[j][p];
        g = g > 0.f ? g : 0.1f * g;              // leaky_relu 0.1
        float xv = s_x[(c0 + j)*180 + rr*36 + (p0 + p) + dw];
        acc[j][p] = fmaf(g, xv, acc[j][p]);
      }
  }

  #pragma unroll
  for (int j = 0; j < 4; j++) {
    float4 o4 = make_float4(acc[j][0], acc[j][1], acc[j][2], acc[j][3]);
    *(float4*)&g_sta[((b*CC + c0 + j)*HIN + h)*WIN + w0 + p0] = o4;
  }
}

// ---------------------------------------------------------------------------
// K3: fused  grid_sample(x) -> expert mix -> grid_sample(sta) -> fusion conv.
// Block: 256 threads, one (batch, output row Y, 64-px segment).
// ---------------------------------------------------------------------------
#define K3_SMEM_FLOATS (8448 + 8448 + 576 + 1024 + 1024 + 512)

__device__ __forceinline__ int catIdx(int px, int col) {
  return px*132 + ((((col >> 2) ^ ((px >> 2) & 7)) << 2) | (col & 3));
}

__global__ __launch_bounds__(256) void k3_fuse(const float* __restrict__ x,
                                               const float* __restrict__ fusw,
                                               const float* __restrict__ fusb,
                                               float* __restrict__ out) {
  extern __shared__ float sm[];
  float* s_fw  = sm;                 // [64][132]  fus_w
  float* s_cat = s_fw + 8448;        // [px 0..63][132 swizzled]: 0..63 sta_hr, 64..127 fea
  float* s_t   = s_cat + 8448;       // [8][72]
  float* s_wc  = s_t + 576;          // [2 parities][512]
  float* s_we  = s_wc + 1024;        // [2][512]
  float* s_tap = s_we + 1024;        // [2 img][64 px][4]: x0,y0,fx,fy

  const int b = blockIdx.z, Y = blockIdx.y, X0 = blockIdx.x * 64;
  const int tid = threadIdx.x;
  const int ph = Y & 1;

  for (int e = tid; e < 8192; e += 256) {
    int o = e >> 7, c = e & 127;
    s_fw[o*132 + c] = fusw[e];
  }
  for (int e = tid; e < 1024; e += 256) {
    int pwx = e >> 9, i = e & 511;
    s_wc[pwx*512 + i] = g_wcpx[ph*2 + pwx][i];
    s_we[pwx*512 + i] = g_wepx[ph*2 + pwx][i];
  }
  if (tid < 128) {
    int img = tid >> 6, px = tid & 63;
    int X = X0 + px; int ci = ph*2 + (X & 1);
    float offx = img ? g_stoff[ci][0] : g_off[ci][0];
    float offy = img ? g_stoff[ci][1] : g_off[ci][1];
    float pxf = (X + 0.5f)*0.5f - 0.5f + offx;
    float pyf = (Y + 0.5f)*0.5f - 0.5f + offy;
    float x0 = floorf(pxf), y0 = floorf(pyf);
    float4 tp = make_float4(x0, y0, pxf - x0, pyf - y0);
    *(float4*)&s_tap[(img*64 + px)*4] = tp;
  }
  __syncthreads();

  // Phase 1: bilinear gathers (zero padding) for both images, all (c, px)
  for (int e = tid; e < 8192; e += 256) {
    int px = e & 63; int c = (e >> 6) & 63; int img = e >> 12;
    float4 tp = *(const float4*)&s_tap[(img*64 + px)*4];
    int ix0 = (int)tp.x, iy0 = (int)tp.y;
    float fx = tp.z, fy = tp.w;
    const float* plane = (img ? g_sta : x) + (b*CC + c)*(HIN*WIN);
    bool xv0 = (unsigned)ix0 < (unsigned)WIN, xv1 = (unsigned)(ix0 + 1) < (unsigned)WIN;
    bool yv0 = (unsigned)iy0 < (unsigned)HIN, yv1 = (unsigned)(iy0 + 1) < (unsigned)HIN;
    float v00 = 0.f, v10 = 0.f, v01 = 0.f, v11 = 0.f;
    if (yv0) { const float* rp = plane + iy0*WIN;
      if (xv0) v00 = rp[ix0]; if (xv1) v10 = rp[ix0 + 1]; }
    if (yv1) { const float* rp = plane + (iy0 + 1)*WIN;
      if (xv0) v01 = rp[ix0]; if (xv1) v11 = rp[ix0 + 1]; }
    float v = (1.f - fy)*((1.f - fx)*v00 + fx*v10) + fy*((1.f - fx)*v01 + fx*v11);
    int col = img ? c : (64 + c);   // sta_hr -> 0..63, fea0 -> 64..127
    s_cat[catIdx(px, col)] = v;
  }
  __syncthreads();

  // Phase 2: t[o][px] = wc_px . fea0
  for (int e = tid; e < 512; e += 256) {
    int o = e >> 6, px = e & 63; int pw = px & 1;
    const float* wrow = s_wc + pw*512 + o*64;
    float a = 0.f;
    #pragma unroll 8
    for (int c = 0; c < 64; c++) a = fmaf(wrow[c], s_cat[catIdx(px, 64 + c)], a);
    s_t[o*72 + px] = a;
  }
  __syncthreads();

  // Phase 3: fea = fea0 + we_px . t  (in place)
  for (int e = tid; e < 4096; e += 256) {
    int px = e & 63, c = e >> 6; int pw = px & 1;
    const float* wrow = s_we + pw*512 + c*8;
    int idx = catIdx(px, 64 + c);
    float a = s_cat[idx];
    #pragma unroll
    for (int o = 0; o < 8; o++) a = fmaf(wrow[o], s_t[o*72 + px], a);
    s_cat[idx] = a;
  }
  __syncthreads();

  // Phase 4: fusion GEMM  out[o][px] = fus_w[o] . cat[px] + fus_b[o]
  const int og = tid >> 4, pg = tid & 15;
  const int o0 = og*4, p0 = pg*4;
  float acc[4][4];
  #pragma unroll
  for (int j = 0; j < 4; j++) {
    float bb = fusb[o0 + j];
    #pragma unroll
    for (int p = 0; p < 4; p++) acc[j][p] = bb;
  }
  #pragma unroll 4
  for (int cq = 0; cq < 32; cq++) {
    float4 fw[4], cv[4];
    #pragma unroll
    for (int j = 0; j < 4; j++) fw[j] = *(const float4*)&s_fw[(o0 + j)*132 + cq*4];
    const int co = ((cq ^ (pg & 7)) << 2);
    #pragma unroll
    for (int p = 0; p < 4; p++) cv[p] = *(const float4*)&s_cat[(p0 + p)*132 + co];
    #pragma unroll
    for (int j = 0; j < 4; j++)
      #pragma unroll
      for (int p = 0; p < 4; p++) {
        acc[j][p] = fmaf(fw[j].x, cv[p].x, acc[j][p]);
        acc[j][p] = fmaf(fw[j].y, cv[p].y, acc[j][p]);
        acc[j][p] = fmaf(fw[j].z, cv[p].z, acc[j][p]);
        acc[j][p] = fmaf(fw[j].w, cv[p].w, acc[j][p]);
      }
  }
  #pragma unroll
  for (int j = 0; j < 4; j++) {
    float4 o4 = make_float4(acc[j][0], acc[j][1], acc[j][2], acc[j][3]);
    *(float4*)&out[((b*CC + o0 + j)*HOUT + Y)*WOUT + X0 + p0] = o4;
  }
}

// ---------------------------------------------------------------------------
extern "C" void kernel_launch(void* const* d_in, const int* in_sizes, int n_in,
                              void* d_out, int out_size) {
  const float* x    = (const float*)d_in[0];
  const float* st   = (const float*)d_in[1];
  const float* kcw  = (const float*)d_in[2];
  const float* kcb  = (const float*)d_in[3];
  const float* wc   = (const float*)d_in[4];
  const float* we   = (const float*)d_in[5];
  const float* b1w  = (const float*)d_in[6];
  const float* b1b  = (const float*)d_in[7];
  const float* b2w  = (const float*)d_in[8];
  const float* b2b  = (const float*)d_in[9];
  const float* rw   = (const float*)d_in[10];
  const float* rb   = (const float*)d_in[11];
  const float* ow   = (const float*)d_in[12];
  const float* ob   = (const float*)d_in[13];
  const float* sow  = (const float*)d_in[14];
  const float* sob  = (const float*)d_in[15];
  const float* fusw = (const float*)d_in[16];
  const float* fusb = (const float*)d_in[17];
  float* out = (float*)d_out;

  const int smem2 = K2_SMEM_FLOATS * 4;
  const int smem3 = K3_SMEM_FLOATS * 4;
  cudaFuncSetAttribute(k2_sta,  cudaFuncAttributeMaxDynamicSharedMemorySize, smem2);
  cudaFuncSetAttribute(k3_fuse, cudaFuncAttributeMaxDynamicSharedMemorySize, smem3);

  k1_parity<<<4, 256>>>(b1w, b1b, b2w, b2b, rw, rb, ow, ob, sow, sob, wc, we);
  k2_sta<<<dim3(WIN/32, HIN, BB), 128, smem2>>>(x, st, kcw, kcb);
  k3_fuse<<<dim3(WOUT/64, HOUT, BB), 256, smem3>>>(x, fusw, fusb, out);
}

// round 3
// speedup vs baseline: 1.5633x; 1.5633x over previous
#include <cuda_runtime.h>
#include <cstdint>

#define BB 4
#define CC 64
#define HIN 96
#define WIN 96
#define HOUT 192
#define WOUT 192

// Scratch + precomputed data (allocation-free rule: device globals)
__device__ float g_sta[BB*CC*HIN*WIN];   // sta_feat  [4,64,96,96]
__device__ float g_off[4][2];
__device__ float g_stoff[4][2];
__device__ float g_wcpx[4][512];         // [o*64+c]
__device__ float g_wepx[4][512];         // [c*8+o]
// kc_w repacked into mma fragment order, hi/lo tf32 split: [25][8 nt][8 ks][32 lane][2]
__device__ float g_bhi[25*4096];
__device__ float g_blo[25*4096];

// ============================ helpers ======================================
__device__ __forceinline__ uint32_t smem_u32(const void* p) {
  uint32_t a;
  asm("{ .reg .u64 t; cvta.to.shared.u64 t, %1; cvt.u32.u64 %0, t; }" : "=r"(a) : "l"(p));
  return a;
}
__device__ __forceinline__ uint32_t to_tf32(float v) {
  uint32_t u; asm("cvt.rna.tf32.f32 %0, %1;" : "=r"(u) : "f"(v)); return u;
}
__device__ __forceinline__ void cp16(uint32_t dst, const float* src) {
  asm volatile("cp.async.cg.shared.global [%0], [%1], 16;" :: "r"(dst), "l"(src));
}
#define CP_COMMIT() asm volatile("cp.async.commit_group;" ::: "memory")
#define CP_WAIT0()  asm volatile("cp.async.wait_group 0;" ::: "memory")

#define MMA_TF32(d, a, b0v, b1v) \
  asm volatile("mma.sync.aligned.m16n8k8.row.col.f32.tf32.tf32.f32 " \
      "{%0,%1,%2,%3}, {%4,%5,%6,%7}, {%8,%9}, {%0,%1,%2,%3};" \
      : "+f"((d)[0]), "+f"((d)[1]), "+f"((d)[2]), "+f"((d)[3]) \
      : "r"((a)[0]), "r"((a)[1]), "r"((a)[2]), "r"((a)[3]), "r"(b0v), "r"(b1v))

// ---------------------------------------------------------------------------
// K0: repack kc_w -> fragment-ordered hi/lo tf32.
// out[((t*8+nt)*8+ks)*64 + l*2 + p]; c = nt*8+(l>>2), k = ks*8+(l&3)+4p
// ---------------------------------------------------------------------------
__global__ void k0_repack(const float* __restrict__ kcw) {
  int idx = blockIdx.x*256 + threadIdx.x;
  if (idx >= 25*2048) return;
  int l  = idx & 31;
  int ks = (idx >> 5) & 7;
  int nt = (idx >> 8) & 7;
  int t  = idx >> 11;
  int c  = nt*8 + (l >> 2);
  int k0 = ks*8 + (l & 3);
  const float* row = kcw + (c*25 + t)*64;
  float v0 = row[k0], v1 = row[k0 + 4];
  uint32_t h0 = to_tf32(v0), h1 = to_tf32(v1);
  g_bhi[idx*2]     = __uint_as_float(h0);
  g_bhi[idx*2 + 1] = __uint_as_float(h1);
  g_blo[idx*2]     = __uint_as_float(to_tf32(v0 - __uint_as_float(h0)));
  g_blo[idx*2 + 1] = __uint_as_float(to_tf32(v1 - __uint_as_float(h1)));
}

// ---------------------------------------------------------------------------
// K1: per-parity MLP -> offsets, st_offsets, routed expert matrices.
// ---------------------------------------------------------------------------
__global__ void k1_parity(const float* __restrict__ b1w, const float* __restrict__ b1b,
                          const float* __restrict__ b2w, const float* __restrict__ b2b,
                          const float* __restrict__ rw,  const float* __restrict__ rb,
                          const float* __restrict__ ow,  const float* __restrict__ ob,
                          const float* __restrict__ sow, const float* __restrict__ sob,
                          const float* __restrict__ wc,  const float* __restrict__ we) {
  __shared__ float hid[64], emb[64], r[4];
  const int ci = blockIdx.x, tid = threadIdx.x;
  const float in2 = (ci >> 1) ? 0.25f : -0.25f;
  const float in3 = (ci & 1)  ? 0.25f : -0.25f;
  if (tid < 64) {
    float a = b1b[tid] + 0.5f*b1w[tid*4+0] + 0.5f*b1w[tid*4+1]
            + in2*b1w[tid*4+2] + in3*b1w[tid*4+3];
    hid[tid] = fmaxf(a, 0.f);
  }
  __syncthreads();
  if (tid < 64) {
    float a = b2b[tid];
    #pragma unroll 8
    for (int k = 0; k < 64; k++) a = fmaf(b2w[tid*64+k], hid[k], a);
    emb[tid] = fmaxf(a, 0.f);
  }
  __syncthreads();
  if (tid < 4) {
    float a = rb[tid];
    for (int k = 0; k < 64; k++) a = fmaf(rw[tid*64+k], emb[k], a);
    r[tid] = 1.f / (1.f + expf(-a));
  } else if (tid < 6) {
    int t = tid - 4; float a = ob[t];
    for (int k = 0; k < 64; k++) a = fmaf(ow[t*64+k], emb[k], a);
    g_off[ci][t] = a;
  } else if (tid < 8) {
    int t = tid - 6; float a = sob[t];
    for (int k = 0; k < 64; k++) a = fmaf(sow[t*64+k], emb[k], a);
    g_stoff[ci][t] = a;
  }
  __syncthreads();
  for (int e = tid; e < 512; e += 256) {
    float a = 0.f, bsum = 0.f;
    #pragma unroll
    for (int ex = 0; ex < 4; ex++) {
      a    = fmaf(r[ex], wc[ex*512+e], a);
      bsum = fmaf(r[ex], we[ex*512+e], bsum);
    }
    g_wcpx[ci][e] = a;
    g_wepx[ci][e] = bsum;
  }
}

// ---------------------------------------------------------------------------
// K2 (mma.sync tf32, 3x-split): fused kernel_warp GEMM + 25-tap sta conv.
// Block: 256 thr / 8 warps, tile = (b, 2 rows, 32 px) x 64 ch.
// warp wid: m-tile = wid&3 (16 px), n-half = wid>>2 (4 n-tiles of 8 ch).
// A (st) fragments hoisted out of the tap loop; B staged per tap via cp.async
// from the K0-repacked fragment-ordered arrays.
// ---------------------------------------------------------------------------
// smem floats: s_b 8192 (hi|lo), s_a 64*66=4224, s_x 64*6*36=13824, s_kb 1600
#define K2_SMEM_FLOATS (8192 + 4224 + 13824 + 1600)

__global__ __launch_bounds__(256, 2) void k2_sta_mma(const float* __restrict__ x,
                                                     const float* __restrict__ st,
                                                     const float* __restrict__ kcb) {
  extern __shared__ float sm[];
  float* s_b  = sm;                // [2][4096] hi, lo
  float* s_a  = sm + 8192;         // [k 64][px 64 pad66]
  float* s_x  = sm + 12416;        // [c 64][row 6][col 36]
  float* s_kb = sm + 26240;        // [1600]

  const int b = blockIdx.z, h0 = blockIdx.y*2, w0 = blockIdx.x*32;
  const int tid = threadIdx.x, wid = tid >> 5, l = tid & 31;
  const int g = l >> 2, tg = l & 3;
  const int mt = wid & 3, nth = wid >> 2;

  // stage A (st) [k][px], coalesced
  for (int e = tid; e < 4096; e += 256) {
    int k = e >> 6, px = e & 63;
    s_a[k*66 + px] = st[((b*CC + k)*HIN + h0 + (px >> 5))*WIN + w0 + (px & 31)];
  }
  // stage x halo [c][6][36], edge-clamped
  for (int e = tid; e < 64*6*36; e += 256) {
    int col = e % 36; int row = (e / 36) % 6; int c = e / 216;
    int gy = min(max(h0 - 2 + row, 0), HIN - 1);
    int gx = min(max(w0 - 2 + col, 0), WIN - 1);
    s_x[e] = x[((b*CC + c)*HIN + gy)*WIN + gx];
  }
  for (int e = tid; e < 1600; e += 256) s_kb[e] = kcb[e];
  __syncthreads();

  // A fragments (hi/lo tf32), tap-invariant: ah/al[ks][4]
  uint32_t ah[8][4], al[8][4];
  {
    const int px0 = mt*16 + g, px1 = px0 + 8;
    #pragma unroll
    for (int ks = 0; ks < 8; ks++) {
      int r0 = (ks*8 + tg)*66, r1 = r0 + 4*66;
      float v0 = s_a[r0 + px0], v1 = s_a[r0 + px1];
      float v2 = s_a[r1 + px0], v3 = s_a[r1 + px1];
      ah[ks][0] = to_tf32(v0); al[ks][0] = to_tf32(v0 - __uint_as_float(ah[ks][0]));
      ah[ks][1] = to_tf32(v1); al[ks][1] = to_tf32(v1 - __uint_as_float(ah[ks][1]));
      ah[ks][2] = to_tf32(v2); al[ks][2] = to_tf32(v2 - __uint_as_float(ah[ks][2]));
      ah[ks][3] = to_tf32(v3); al[ks][3] = to_tf32(v3 - __uint_as_float(ah[ks][3]));
    }
  }

  float sacc[16];
  #pragma unroll
  for (int i = 0; i < 16; i++) sacc[i] = 0.f;

  const uint32_t sb = smem_u32(s_b);
  const int prow = mt >> 1, pcol0 = (mt & 1)*16 + g;

  for (int t = 0; t < 25; t++) {
    // ---- stage B (32KB) via cp.async, fragment-ordered ----
    {
      const float* srch = g_bhi + t*4096;
      const float* srcl = g_blo + t*4096;
      #pragma unroll
      for (int i = 0; i < 4; i++) {
        int j = tid + i*256;                       // 0..1023 16B chunks
        cp16(sb + (uint32_t)j*16u,           srch + j*4);
        cp16(sb + 16384u + (uint32_t)j*16u,  srcl + j*4);
      }
      CP_COMMIT(); CP_WAIT0();
      __syncthreads();
    }

    const int rr = t / 5, dw = t - rr*5;

    // d-regs initialized with bias kcb[c*25+t]
    float d[4][4];
    #pragma unroll
    for (int n = 0; n < 4; n++) {
      int c0 = ((nth*4 + n)*8 + 2*tg)*25 + t;
      d[n][0] = s_kb[c0];      d[n][1] = s_kb[c0 + 25];
      d[n][2] = d[n][0];       d[n][3] = d[n][1];
    }

    #pragma unroll
    for (int ks = 0; ks < 8; ks++) {
      #pragma unroll
      for (int n = 0; n < 4; n++) {
        int bo = ((nth*4 + n)*8 + ks)*64 + l*2;
        float2 bh = *(const float2*)&s_b[bo];
        float2 bl = *(const float2*)&s_b[4096 + bo];
        uint32_t bh0 = __float_as_uint(bh.x), bh1 = __float_as_uint(bh.y);
        uint32_t bl0 = __float_as_uint(bl.x), bl1 = __float_as_uint(bl.y);
        MMA_TF32(d[n], ah[ks], bh0, bh1);
        MMA_TF32(d[n], ah[ks], bl0, bl1);
        MMA_TF32(d[n], al[ks], bh0, bh1);
      }
    }

    // epilogue: lrelu(gate) * x_halo, accumulate
    #pragma unroll
    for (int n = 0; n < 4; n++) {
      int cb = (nth*4 + n)*8 + 2*tg;
      #pragma unroll
      for (int j = 0; j < 4; j++) {
        int c  = cb + (j & 1);
        int px = pcol0 + (j >> 1)*8;
        float gv = d[n][j];
        float lv = fmaf(0.45f, fabsf(gv), 0.55f*gv);        // leaky_relu 0.1
        float xv = s_x[c*216 + (prow + rr)*36 + px + dw];
        sacc[n*4 + j] = fmaf(lv, xv, sacc[n*4 + j]);
      }
    }
    __syncthreads();   // s_b consumed before next tap's overwrite
  }

  // store sta_feat
  #pragma unroll
  for (int n = 0; n < 4; n++) {
    int cb = (nth*4 + n)*8 + 2*tg;
    #pragma unroll
    for (int j = 0; j < 4; j++) {
      int c  = cb + (j & 1);
      int px = pcol0 + (j >> 1)*8;
      g_sta[((b*CC + c)*HIN + h0 + prow)*WIN + w0 + px] = sacc[n*4 + j];
    }
  }
}

// ---------------------------------------------------------------------------
// K3: fused  grid_sample(x) -> expert mix -> grid_sample(sta) -> fusion conv.
// ---------------------------------------------------------------------------
#define K3_SMEM_FLOATS (8448 + 8448 + 576 + 1024 + 1024 + 512)

__device__ __forceinline__ int catIdx(int px, int col) {
  return px*132 + ((((col >> 2) ^ ((px >> 2) & 7)) << 2) | (col & 3));
}

__global__ __launch_bounds__(256) void k3_fuse(const float* __restrict__ x,
                                               const float* __restrict__ fusw,
                                               const float* __restrict__ fusb,
                                               float* __restrict__ out) {
  extern __shared__ float sm[];
  float* s_fw  = sm;                 // [64][132]
  float* s_cat = s_fw + 8448;        // [px][132 swizzled]
  float* s_t   = s_cat + 8448;       // [8][72]
  float* s_wc  = s_t + 576;          // [2][512]
  float* s_we  = s_wc + 1024;        // [2][512]
  float* s_tap = s_we + 1024;        // [2][64][4]

  const int b = blockIdx.z, Y = blockIdx.y, X0 = blockIdx.x * 64;
  const int tid = threadIdx.x;
  const int ph = Y & 1;

  for (int e = tid; e < 8192; e += 256) {
    int o = e >> 7, c = e & 127;
    s_fw[o*132 + c] = fusw[e];
  }
  for (int e = tid; e < 1024; e += 256) {
    int pwx = e >> 9, i = e & 511;
    s_wc[pwx*512 + i] = g_wcpx[ph*2 + pwx][i];
    s_we[pwx*512 + i] = g_wepx[ph*2 + pwx][i];
  }
  if (tid < 128) {
    int img = tid >> 6, px = tid & 63;
    int X = X0 + px; int ci = ph*2 + (X & 1);
    float offx = img ? g_stoff[ci][0] : g_off[ci][0];
    float offy = img ? g_stoff[ci][1] : g_off[ci][1];
    float pxf = (X + 0.5f)*0.5f - 0.5f + offx;
    float pyf = (Y + 0.5f)*0.5f - 0.5f + offy;
    float x0 = floorf(pxf), y0 = floorf(pyf);
    float4 tp = make_float4(x0, y0, pxf - x0, pyf - y0);
    *(float4*)&s_tap[(img*64 + px)*4] = tp;
  }
  __syncthreads();

  for (int e = tid; e < 8192; e += 256) {
    int px = e & 63; int c = (e >> 6) & 63; int img = e >> 12;
    float4 tp = *(const float4*)&s_tap[(img*64 + px)*4];
    int ix0 = (int)tp.x, iy0 = (int)tp.y;
    float fx = tp.z, fy = tp.w;
    const float* plane = (img ? g_sta : x) + (b*CC + c)*(HIN*WIN);
    bool xv0 = (unsigned)ix0 < (unsigned)WIN, xv1 = (unsigned)(ix0 + 1) < (unsigned)WIN;
    bool yv0 = (unsigned)iy0 < (unsigned)HIN, yv1 = (unsigned)(iy0 + 1) < (unsigned)HIN;
    float v00 = 0.f, v10 = 0.f, v01 = 0.f, v11 = 0.f;
    if (yv0) { const float* rp = plane + iy0*WIN;
      if (xv0) v00 = rp[ix0]; if (xv1) v10 = rp[ix0 + 1]; }
    if (yv1) { const float* rp = plane + (iy0 + 1)*WIN;
      if (xv0) v01 = rp[ix0]; if (xv1) v11 = rp[ix0 + 1]; }
    float v = (1.f - fy)*((1.f - fx)*v00 + fx*v10) + fy*((1.f - fx)*v01 + fx*v11);
    int col = img ? c : (64 + c);
    s_cat[catIdx(px, col)] = v;
  }
  __syncthreads();

  for (int e = tid; e < 512; e += 256) {
    int o = e >> 6, px = e & 63; int pw = px & 1;
    const float* wrow = s_wc + pw*512 + o*64;
    float a = 0.f;
    #pragma unroll 8
    for (int c = 0; c < 64; c++) a = fmaf(wrow[c], s_cat[catIdx(px, 64 + c)], a);
    s_t[o*72 + px] = a;
  }
  __syncthreads();

  for (int e = tid; e < 4096; e += 256) {
    int px = e & 63, c = e >> 6; int pw = px & 1;
    const float* wrow = s_we + pw*512 + c*8;
    int idx = catIdx(px, 64 + c);
    float a = s_cat[idx];
    #pragma unroll
    for (int o = 0; o < 8; o++) a = fmaf(wrow[o], s_t[o*72 + px], a);
    s_cat[idx] = a;
  }
  __syncthreads();

  const int og = tid >> 4, pg = tid & 15;
  const int o0 = og*4, p0 = pg*4;
  float acc[4][4];
  #pragma unroll
  for (int j = 0; j < 4; j++) {
    float bb = fusb[o0 + j];
    #pragma unroll
    for (int p = 0; p < 4; p++) acc[j][p] = bb;
  }
  #pragma unroll 4
  for (int cq = 0; cq < 32; cq++) {
    float4 fw[4], cv[4];
    #pragma unroll
    for (int j = 0; j < 4; j++) fw[j] = *(const float4*)&s_fw[(o0 + j)*132 + cq*4];
    const int co = ((cq ^ (pg & 7)) << 2);
    #pragma unroll
    for (int p = 0; p < 4; p++) cv[p] = *(const float4*)&s_cat[(p0 + p)*132 + co];
    #pragma unroll
    for (int j = 0; j < 4; j++)
      #pragma unroll
      for (int p = 0; p < 4; p++) {
        acc[j][p] = fmaf(fw[j].x, cv[p].x, acc[j][p]);
        acc[j][p] = fmaf(fw[j].y, cv[p].y, acc[j][p]);
        acc[j][p] = fmaf(fw[j].z, cv[p].z, acc[j][p]);
        acc[j][p] = fmaf(fw[j].w, cv[p].w, acc[j][p]);
      }
  }
  #pragma unroll
  for (int j = 0; j < 4; j++) {
    float4 o4 = make_float4(acc[j][0], acc[j][1], acc[j][2], acc[j][3]);
    *(float4*)&out[((b*CC + o0 + j)*HOUT + Y)*WOUT + X0 + p0] = o4;
  }
}

// ---------------------------------------------------------------------------
extern "C" void kernel_launch(void* const* d_in, const int* in_sizes, int n_in,
                              void* d_out, int out_size) {
  const float* x    = (const float*)d_in[0];
  const float* st   = (const float*)d_in[1];
  const float* kcw  = (const float*)d_in[2];
  const float* kcb  = (const float*)d_in[3];
  const float* wc   = (const float*)d_in[4];
  const float* we   = (const float*)d_in[5];
  const float* b1w  = (const float*)d_in[6];
  const float* b1b  = (const float*)d_in[7];
  const float* b2w  = (const float*)d_in[8];
  const float* b2b  = (const float*)d_in[9];
  const float* rw   = (const float*)d_in[10];
  const float* rb   = (const float*)d_in[11];
  const float* ow   = (const float*)d_in[12];
  const float* ob   = (const float*)d_in[13];
  const float* sow  = (const float*)d_in[14];
  const float* sob  = (const float*)d_in[15];
  const float* fusw = (const float*)d_in[16];
  const float* fusb = (const float*)d_in[17];
  float* out = (float*)d_out;

  const int smem2 = K2_SMEM_FLOATS * 4;
  const int smem3 = K3_SMEM_FLOATS * 4;
  cudaFuncSetAttribute(k2_sta_mma, cudaFuncAttributeMaxDynamicSharedMemorySize, smem2);
  cudaFuncSetAttribute(k3_fuse,    cudaFuncAttributeMaxDynamicSharedMemorySize, smem3);

  k0_repack<<<200, 256>>>(kcw);
  k1_parity<<<4, 256>>>(b1w, b1b, b2w, b2b, rw, rb, ow, ob, sow, sob, wc, we);
  k2_sta_mma<<<dim3(WIN/32, HIN/2, BB), 256, smem2>>>(x, st, kcb);
  k3_fuse<<<dim3(WOUT/64, HOUT, BB), 256, smem3>>>(x, fusw, fusb, out);
}

// round 4
// speedup vs baseline: 1.7124x; 1.0954x over previous
#include <cuda_runtime.h>
#include <cstdint>

#define BB 4
#define CC 64
#define HIN 96
#define WIN 96
#define HOUT 192
#define WOUT 192

// Scratch + precomputed data (allocation-free rule: device globals)
__device__ float g_sta[BB*CC*HIN*WIN];   // sta_feat  [4,64,96,96]
__device__ float g_off[4][2];
__device__ float g_stoff[4][2];
__device__ float g_wcpx[4][512];         // [o*64+c]
__device__ float g_wepx[4][512];         // [c*8+o]
// kc_w repacked into mma fragment order, hi/lo tf32 split: [25][8 nt][8 ks][32 lane][2]
__device__ float g_bhi[25*4096];
__device__ float g_blo[25*4096];

// ============================ helpers ======================================
__device__ __forceinline__ uint32_t smem_u32(const void* p) {
  uint32_t a;
  asm("{ .reg .u64 t; cvta.to.shared.u64 t, %1; cvt.u32.u64 %0, t; }" : "=r"(a) : "l"(p));
  return a;
}
__device__ __forceinline__ uint32_t to_tf32(float v) {
  uint32_t u; asm("cvt.rna.tf32.f32 %0, %1;" : "=r"(u) : "f"(v)); return u;
}
__device__ __forceinline__ void cp16(uint32_t dst, const float* src) {
  asm volatile("cp.async.cg.shared.global [%0], [%1], 16;" :: "r"(dst), "l"(src));
}
#define CP_COMMIT() asm volatile("cp.async.commit_group;" ::: "memory")
#define CP_WAIT0()  asm volatile("cp.async.wait_group 0;" ::: "memory")

#define MMA_TF32(d, a, b0v, b1v) \
  asm volatile("mma.sync.aligned.m16n8k8.row.col.f32.tf32.tf32.f32 " \
      "{%0,%1,%2,%3}, {%4,%5,%6,%7}, {%8,%9}, {%0,%1,%2,%3};" \
      : "+f"((d)[0]), "+f"((d)[1]), "+f"((d)[2]), "+f"((d)[3]) \
      : "r"((a)[0]), "r"((a)[1]), "r"((a)[2]), "r"((a)[3]), "r"(b0v), "r"(b1v))

// ---------------------------------------------------------------------------
// K0: repack kc_w -> fragment-ordered hi/lo tf32.
// out[((t*8+nt)*8+ks)*64 + l*2 + p]; c = nt*8+(l>>2), k = ks*8+(l&3)+4p
// ---------------------------------------------------------------------------
__global__ void k0_repack(const float* __restrict__ kcw) {
  int idx = blockIdx.x*256 + threadIdx.x;
  if (idx >= 25*2048) return;
  int l  = idx & 31;
  int ks = (idx >> 5) & 7;
  int nt = (idx >> 8) & 7;
  int t  = idx >> 11;
  int c  = nt*8 + (l >> 2);
  int k0 = ks*8 + (l & 3);
  const float* row = kcw + (c*25 + t)*64;
  float v0 = row[k0], v1 = row[k0 + 4];
  uint32_t h0 = to_tf32(v0), h1 = to_tf32(v1);
  g_bhi[idx*2]     = __uint_as_float(h0);
  g_bhi[idx*2 + 1] = __uint_as_float(h1);
  g_blo[idx*2]     = __uint_as_float(to_tf32(v0 - __uint_as_float(h0)));
  g_blo[idx*2 + 1] = __uint_as_float(to_tf32(v1 - __uint_as_float(h1)));
}

// ---------------------------------------------------------------------------
// K1: per-parity MLP -> offsets, st_offsets, routed expert matrices.
// ---------------------------------------------------------------------------
__global__ void k1_parity(const float* __restrict__ b1w, const float* __restrict__ b1b,
                          const float* __restrict__ b2w, const float* __restrict__ b2b,
                          const float* __restrict__ rw,  const float* __restrict__ rb,
                          const float* __restrict__ ow,  const float* __restrict__ ob,
                          const float* __restrict__ sow, const float* __restrict__ sob,
                          const float* __restrict__ wc,  const float* __restrict__ we) {
  __shared__ float hid[64], emb[64], r[4];
  const int ci = blockIdx.x, tid = threadIdx.x;
  const float in2 = (ci >> 1) ? 0.25f : -0.25f;
  const float in3 = (ci & 1)  ? 0.25f : -0.25f;
  if (tid < 64) {
    float a = b1b[tid] + 0.5f*b1w[tid*4+0] + 0.5f*b1w[tid*4+1]
            + in2*b1w[tid*4+2] + in3*b1w[tid*4+3];
    hid[tid] = fmaxf(a, 0.f);
  }
  __syncthreads();
  if (tid < 64) {
    float a = b2b[tid];
    #pragma unroll 8
    for (int k = 0; k < 64; k++) a = fmaf(b2w[tid*64+k], hid[k], a);
    emb[tid] = fmaxf(a, 0.f);
  }
  __syncthreads();
  if (tid < 4) {
    float a = rb[tid];
    for (int k = 0; k < 64; k++) a = fmaf(rw[tid*64+k], emb[k], a);
    r[tid] = 1.f / (1.f + expf(-a));
  } else if (tid < 6) {
    int t = tid - 4; float a = ob[t];
    for (int k = 0; k < 64; k++) a = fmaf(ow[t*64+k], emb[k], a);
    g_off[ci][t] = a;
  } else if (tid < 8) {
    int t = tid - 6; float a = sob[t];
    for (int k = 0; k < 64; k++) a = fmaf(sow[t*64+k], emb[k], a);
    g_stoff[ci][t] = a;
  }
  __syncthreads();
  for (int e = tid; e < 512; e += 256) {
    float a = 0.f, bsum = 0.f;
    #pragma unroll
    for (int ex = 0; ex < 4; ex++) {
      a    = fmaf(r[ex], wc[ex*512+e], a);
      bsum = fmaf(r[ex], we[ex*512+e], bsum);
    }
    g_wcpx[ci][e] = a;
    g_wepx[ci][e] = bsum;
  }
}

// ---------------------------------------------------------------------------
// K2 (mma.sync tf32, 3x-split): fused kernel_warp GEMM + 25-tap sta conv.
// ---------------------------------------------------------------------------
#define K2_SMEM_FLOATS (8192 + 4224 + 13824 + 1600)

__global__ __launch_bounds__(256, 2) void k2_sta_mma(const float* __restrict__ x,
                                                     const float* __restrict__ st,
                                                     const float* __restrict__ kcb) {
  extern __shared__ float sm[];
  float* s_b  = sm;                // [2][4096] hi, lo
  float* s_a  = sm + 8192;         // [k 64][px 64 pad66]
  float* s_x  = sm + 12416;        // [c 64][row 6][col 36]
  float* s_kb = sm + 26240;        // [1600]

  const int b = blockIdx.z, h0 = blockIdx.y*2, w0 = blockIdx.x*32;
  const int tid = threadIdx.x, wid = tid >> 5, l = tid & 31;
  const int g = l >> 2, tg = l & 3;
  const int mt = wid & 3, nth = wid >> 2;

  for (int e = tid; e < 4096; e += 256) {
    int k = e >> 6, px = e & 63;
    s_a[k*66 + px] = st[((b*CC + k)*HIN + h0 + (px >> 5))*WIN + w0 + (px & 31)];
  }
  for (int e = tid; e < 64*6*36; e += 256) {
    int col = e % 36; int row = (e / 36) % 6; int c = e / 216;
    int gy = min(max(h0 - 2 + row, 0), HIN - 1);
    int gx = min(max(w0 - 2 + col, 0), WIN - 1);
    s_x[e] = x[((b*CC + c)*HIN + gy)*WIN + gx];
  }
  for (int e = tid; e < 1600; e += 256) s_kb[e] = kcb[e];
  __syncthreads();

  uint32_t ah[8][4], al[8][4];
  {
    const int px0 = mt*16 + g, px1 = px0 + 8;
    #pragma unroll
    for (int ks = 0; ks < 8; ks++) {
      int r0 = (ks*8 + tg)*66, r1 = r0 + 4*66;
      float v0 = s_a[r0 + px0], v1 = s_a[r0 + px1];
      float v2 = s_a[r1 + px0], v3 = s_a[r1 + px1];
      ah[ks][0] = to_tf32(v0); al[ks][0] = to_tf32(v0 - __uint_as_float(ah[ks][0]));
      ah[ks][1] = to_tf32(v1); al[ks][1] = to_tf32(v1 - __uint_as_float(ah[ks][1]));
      ah[ks][2] = to_tf32(v2); al[ks][2] = to_tf32(v2 - __uint_as_float(ah[ks][2]));
      ah[ks][3] = to_tf32(v3); al[ks][3] = to_tf32(v3 - __uint_as_float(ah[ks][3]));
    }
  }

  float sacc[16];
  #pragma unroll
  for (int i = 0; i < 16; i++) sacc[i] = 0.f;

  const uint32_t sb = smem_u32(s_b);
  const int prow = mt >> 1, pcol0 = (mt & 1)*16 + g;

  for (int t = 0; t < 25; t++) {
    {
      const float* srch = g_bhi + t*4096;
      const float* srcl = g_blo + t*4096;
      #pragma unroll
      for (int i = 0; i < 4; i++) {
        int j = tid + i*256;
        cp16(sb + (uint32_t)j*16u,           srch + j*4);
        cp16(sb + 16384u + (uint32_t)j*16u,  srcl + j*4);
      }
      CP_COMMIT(); CP_WAIT0();
      __syncthreads();
    }

    const int rr = t / 5, dw = t - rr*5;

    float d[4][4];
    #pragma unroll
    for (int n = 0; n < 4; n++) {
      int c0 = ((nth*4 + n)*8 + 2*tg)*25 + t;
      d[n][0] = s_kb[c0];      d[n][1] = s_kb[c0 + 25];
      d[n][2] = d[n][0];       d[n][3] = d[n][1];
    }

    #pragma unroll
    for (int ks = 0; ks < 8; ks++) {
      #pragma unroll
      for (int n = 0; n < 4; n++) {
        int bo = ((nth*4 + n)*8 + ks)*64 + l*2;
        float2 bh = *(const float2*)&s_b[bo];
        float2 bl = *(const float2*)&s_b[4096 + bo];
        uint32_t bh0 = __float_as_uint(bh.x), bh1 = __float_as_uint(bh.y);
        uint32_t bl0 = __float_as_uint(bl.x), bl1 = __float_as_uint(bl.y);
        MMA_TF32(d[n], ah[ks], bh0, bh1);
        MMA_TF32(d[n], ah[ks], bl0, bl1);
        MMA_TF32(d[n], al[ks], bh0, bh1);
      }
    }

    #pragma unroll
    for (int n = 0; n < 4; n++) {
      int cb = (nth*4 + n)*8 + 2*tg;
      #pragma unroll
      for (int j = 0; j < 4; j++) {
        int c  = cb + (j & 1);
        int px = pcol0 + (j >> 1)*8;
        float gv = d[n][j];
        float lv = fmaf(0.45f, fabsf(gv), 0.55f*gv);
        float xv = s_x[c*216 + (prow + rr)*36 + px + dw];
        sacc[n*4 + j] = fmaf(lv, xv, sacc[n*4 + j]);
      }
    }
    __syncthreads();
  }

  #pragma unroll
  for (int n = 0; n < 4; n++) {
    int cb = (nth*4 + n)*8 + 2*tg;
    #pragma unroll
    for (int j = 0; j < 4; j++) {
      int c  = cb + (j & 1);
      int px = pcol0 + (j >> 1)*8;
      g_sta[((b*CC + c)*HIN + h0 + prow)*WIN + w0 + px] = sacc[n*4 + j];
    }
  }
}

// ---------------------------------------------------------------------------
// K3 v2: fused grid_sample(x) -> expert mix -> grid_sample(sta) -> fusion conv.
// No fus_w smem staging (read via __ldg, broadcast), precomputed gather
// descriptors (clamped offsets + validity-zeroed weights).
// smem floats: 8448 + 576 + 1024 + 1024 + 512(int) + 512 = ~48KB
// ---------------------------------------------------------------------------
#define K3_SMEM_FLOATS (8448 + 576 + 1024 + 1024 + 512 + 512)

__device__ __forceinline__ int catIdx(int px, int col) {
  return px*132 + ((((col >> 2) ^ ((px >> 2) & 7)) << 2) | (col & 3));
}

__global__ __launch_bounds__(256, 3) void k3_fuse(const float* __restrict__ x,
                                                  const float* __restrict__ fusw,
                                                  const float* __restrict__ fusb,
                                                  float* __restrict__ out) {
  extern __shared__ float sm[];
  float* s_cat = sm;                 // [px][132 swizzled]: 0..63 sta_hr, 64..127 fea
  float* s_t   = s_cat + 8448;       // [8][72]
  float* s_wc  = s_t + 576;          // [2][512]
  float* s_we  = s_wc + 1024;        // [2][512]
  int4*  s_gi  = (int4*)(s_we + 1024);        // [2 img][64 px] clamped offsets
  float4* s_gw = (float4*)(s_we + 1024 + 512); // [2 img][64 px] weights

  const int b = blockIdx.z, Y = blockIdx.y, X0 = blockIdx.x * 64;
  const int tid = threadIdx.x;
  const int ph = Y & 1;

  for (int e = tid; e < 1024; e += 256) {
    int pwx = e >> 9, i = e & 511;
    s_wc[pwx*512 + i] = g_wcpx[ph*2 + pwx][i];
    s_we[pwx*512 + i] = g_wepx[ph*2 + pwx][i];
  }
  if (tid < 128) {
    int img = tid >> 6, px = tid & 63;
    int X = X0 + px; int ci = ph*2 + (X & 1);
    float offx = img ? g_stoff[ci][0] : g_off[ci][0];
    float offy = img ? g_stoff[ci][1] : g_off[ci][1];
    float pxf = (X + 0.5f)*0.5f - 0.5f + offx;
    float pyf = (Y + 0.5f)*0.5f - 0.5f + offy;
    float x0f = floorf(pxf), y0f = floorf(pyf);
    int ix0 = (int)x0f, iy0 = (int)y0f;
    float fx = pxf - x0f, fy = pyf - y0f;
    float wx0 = 1.f - fx, wy0 = 1.f - fy;
    bool xv0 = (unsigned)ix0 < (unsigned)WIN, xv1 = (unsigned)(ix0+1) < (unsigned)WIN;
    bool yv0 = (unsigned)iy0 < (unsigned)HIN, yv1 = (unsigned)(iy0+1) < (unsigned)HIN;
    int cx0 = min(max(ix0, 0), WIN-1), cx1 = min(max(ix0+1, 0), WIN-1);
    int cy0 = min(max(iy0, 0), HIN-1)*WIN, cy1 = min(max(iy0+1, 0), HIN-1)*WIN;
    s_gi[tid] = make_int4(cy0+cx0, cy0+cx1, cy1+cx0, cy1+cx1);
    s_gw[tid] = make_float4((yv0 && xv0) ? wy0*wx0 : 0.f,
                            (yv0 && xv1) ? wy0*fx  : 0.f,
                            (yv1 && xv0) ? fy*wx0  : 0.f,
                            (yv1 && xv1) ? fy*fx   : 0.f);
  }
  __syncthreads();

  // Phase 1: bilinear gathers via precomputed descriptors
  for (int e = tid; e < 8192; e += 256) {
    int px = e & 63; int c = (e >> 6) & 63; int img = e >> 12;
    const float* plane = (img ? g_sta : x) + (b*CC + c)*(HIN*WIN);
    int4  o = s_gi[img*64 + px];
    float4 wv = s_gw[img*64 + px];
    float v = wv.x*__ldg(plane + o.x) + wv.y*__ldg(plane + o.y)
            + wv.z*__ldg(plane + o.z) + wv.w*__ldg(plane + o.w);
    int col = img ? c : (64 + c);
    s_cat[catIdx(px, col)] = v;
  }
  __syncthreads();

  // Phase 2: t[o][px] = wc_px . fea0
  for (int e = tid; e < 512; e += 256) {
    int o = e >> 6, px = e & 63; int pw = px & 1;
    const float* wrow = s_wc + pw*512 + o*64;
    float a = 0.f;
    #pragma unroll 8
    for (int c = 0; c < 64; c++) a = fmaf(wrow[c], s_cat[catIdx(px, 64 + c)], a);
    s_t[o*72 + px] = a;
  }
  __syncthreads();

  // Phase 3: fea = fea0 + we_px . t  (in place)
  for (int e = tid; e < 4096; e += 256) {
    int px = e & 63, c = e >> 6; int pw = px & 1;
    const float* wrow = s_we + pw*512 + c*8;
    int idx = catIdx(px, 64 + c);
    float a = s_cat[idx];
    #pragma unroll
    for (int o = 0; o < 8; o++) a = fmaf(wrow[o], s_t[o*72 + px], a);
    s_cat[idx] = a;
  }
  __syncthreads();

  // Phase 4: fusion GEMM, fus_w read straight from gmem (broadcast, L1-hot)
  const int og = tid >> 4, pg = tid & 15;
  const int o0 = og*4, p0 = pg*4;
  float acc[4][4];
  #pragma unroll
  for (int j = 0; j < 4; j++) {
    float bb = __ldg(fusb + o0 + j);
    #pragma unroll
    for (int p = 0; p < 4; p++) acc[j][p] = bb;
  }
  #pragma unroll 4
  for (int cq = 0; cq < 32; cq++) {
    float4 fw[4], cv[4];
    #pragma unroll
    for (int j = 0; j < 4; j++)
      fw[j] = __ldg((const float4*)(fusw + (o0 + j)*128 + cq*4));
    const int co = ((cq ^ (pg & 7)) << 2);
    #pragma unroll
    for (int p = 0; p < 4; p++) cv[p] = *(const float4*)&s_cat[(p0 + p)*132 + co];
    #pragma unroll
    for (int j = 0; j < 4; j++)
      #pragma unroll
      for (int p = 0; p < 4; p++) {
        acc[j][p] = fmaf(fw[j].x, cv[p].x, acc[j][p]);
        acc[j][p] = fmaf(fw[j].y, cv[p].y, acc[j][p]);
        acc[j][p] = fmaf(fw[j].z, cv[p].z, acc[j][p]);
        acc[j][p] = fmaf(fw[j].w, cv[p].w, acc[j][p]);
      }
  }
  #pragma unroll
  for (int j = 0; j < 4; j++) {
    float4 o4 = make_float4(acc[j][0], acc[j][1], acc[j][2], acc[j][3]);
    *(float4*)&out[((b*CC + o0 + j)*HOUT + Y)*WOUT + X0 + p0] = o4;
  }
}

// ---------------------------------------------------------------------------
extern "C" void kernel_launch(void* const* d_in, const int* in_sizes, int n_in,
                              void* d_out, int out_size) {
  const float* x    = (const float*)d_in[0];
  const float* st   = (const float*)d_in[1];
  const float* kcw  = (const float*)d_in[2];
  const float* kcb  = (const float*)d_in[3];
  const float* wc   = (const float*)d_in[4];
  const float* we   = (const float*)d_in[5];
  const float* b1w  = (const float*)d_in[6];
  const float* b1b  = (const float*)d_in[7];
  const float* b2w  = (const float*)d_in[8];
  const float* b2b  = (const float*)d_in[9];
  const float* rw   = (const float*)d_in[10];
  const float* rb   = (const float*)d_in[11];
  const float* ow   = (const float*)d_in[12];
  const float* ob   = (const float*)d_in[13];
  const float* sow  = (const float*)d_in[14];
  const float* sob  = (const float*)d_in[15];
  const float* fusw = (const float*)d_in[16];
  const float* fusb = (const float*)d_in[17];
  float* out = (float*)d_out;

  const int smem2 = K2_SMEM_FLOATS * 4;
  const int smem3 = K3_SMEM_FLOATS * 4;
  cudaFuncSetAttribute(k2_sta_mma, cudaFuncAttributeMaxDynamicSharedMemorySize, smem2);
  cudaFuncSetAttribute(k3_fuse,    cudaFuncAttributeMaxDynamicSharedMemorySize, smem3);

  k0_repack<<<200, 256>>>(kcw);
  k1_parity<<<4, 256>>>(b1w, b1b, b2w, b2b, rw, rb, ow, ob, sow, sob, wc, we);
  k2_sta_mma<<<dim3(WIN/32, HIN/2, BB), 256, smem2>>>(x, st, kcb);
  k3_fuse<<<dim3(WOUT/64, HOUT, BB), 256, smem3>>>(x, fusw, fusb, out);
}

// round 5
// speedup vs baseline: 1.9337x; 1.1293x over previous
#include <cuda_runtime.h>
#include <cstdint>

#define BB 4
#define CC 64
#define HIN 96
#define WIN 96
#define HOUT 192
#define WOUT 192
#define NPX (HIN*WIN)          // 9216

// Scratch + precomputed data (allocation-free rule: device globals)
__device__ float g_sta[BB*CC*NPX];       // sta_feat  [b][c][96][96]
__device__ float g_A[BB*NPX*CC];         // fusL@sta, channel-last [b][px][64]
__device__ float g_B[BB*NPX*CC];         // fusR@x,   channel-last
__device__ float g_X[BB*NPX*CC];         // x transposed, channel-last
__device__ float g_off[4][2];
__device__ float g_stoff[4][2];
__device__ float g_wcpx[4][512];         // [o*64+c]
__device__ float g_M[4][512];            // [j*64+o]  (fusR @ we_par)
// kc_w repacked into mma fragment order, hi/lo tf32 split
__device__ float g_bhi[25*4096];
__device__ float g_blo[25*4096];

// ============================ helpers ======================================
__device__ __forceinline__ uint32_t smem_u32(const void* p) {
  uint32_t a;
  asm("{ .reg .u64 t; cvta.to.shared.u64 t, %1; cvt.u32.u64 %0, t; }" : "=r"(a) : "l"(p));
  return a;
}
__device__ __forceinline__ uint32_t to_tf32(float v) {
  uint32_t u; asm("cvt.rna.tf32.f32 %0, %1;" : "=r"(u) : "f"(v)); return u;
}
__device__ __forceinline__ void cp16(uint32_t dst, const float* src) {
  asm volatile("cp.async.cg.shared.global [%0], [%1], 16;" :: "r"(dst), "l"(src));
}
#define CP_COMMIT() asm volatile("cp.async.commit_group;" ::: "memory")
#define CP_WAIT0()  asm volatile("cp.async.wait_group 0;" ::: "memory")

#define MMA_TF32(d, a, b0v, b1v) \
  asm volatile("mma.sync.aligned.m16n8k8.row.col.f32.tf32.tf32.f32 " \
      "{%0,%1,%2,%3}, {%4,%5,%6,%7}, {%8,%9}, {%0,%1,%2,%3};" \
      : "+f"((d)[0]), "+f"((d)[1]), "+f"((d)[2]), "+f"((d)[3]) \
      : "r"((a)[0]), "r"((a)[1]), "r"((a)[2]), "r"((a)[3]), "r"(b0v), "r"(b1v))

// ---------------------------------------------------------------------------
// K01: blocks 0..199 repack kc_w; blocks 200..203 per-parity MLP + M matrices
// ---------------------------------------------------------------------------
__global__ void k01_prep(const float* __restrict__ kcw,
                         const float* __restrict__ b1w, const float* __restrict__ b1b,
                         const float* __restrict__ b2w, const float* __restrict__ b2b,
                         const float* __restrict__ rw,  const float* __restrict__ rb,
                         const float* __restrict__ ow,  const float* __restrict__ ob,
                         const float* __restrict__ sow, const float* __restrict__ sob,
                         const float* __restrict__ wc,  const float* __restrict__ we,
                         const float* __restrict__ fusw) {
  const int tid = threadIdx.x;
  if (blockIdx.x < 200) {
    int idx = blockIdx.x*256 + tid;
    if (idx >= 25*2048) return;
    int l  = idx & 31;
    int ks = (idx >> 5) & 7;
    int nt = (idx >> 8) & 7;
    int t  = idx >> 11;
    int c  = nt*8 + (l >> 2);
    int k0 = ks*8 + (l & 3);
    const float* row = kcw + (c*25 + t)*64;
    float v0 = row[k0], v1 = row[k0 + 4];
    uint32_t h0 = to_tf32(v0), h1 = to_tf32(v1);
    g_bhi[idx*2]     = __uint_as_float(h0);
    g_bhi[idx*2 + 1] = __uint_as_float(h1);
    g_blo[idx*2]     = __uint_as_float(to_tf32(v0 - __uint_as_float(h0)));
    g_blo[idx*2 + 1] = __uint_as_float(to_tf32(v1 - __uint_as_float(h1)));
    return;
  }
  // ---- parity branch ----
  __shared__ float hid[64], emb[64], r[4];
  __shared__ float s_we2[512];     // we_px [c*8+j]
  __shared__ float s_fr[64*65];    // fusR^T [c][o] padded
  const int ci = blockIdx.x - 200;
  const float in2 = (ci >> 1) ? 0.25f : -0.25f;
  const float in3 = (ci & 1)  ? 0.25f : -0.25f;

  // stage fusR^T (coalesced read over c, pad-65 write)
  for (int e = tid; e < 4096; e += 256) {
    int o = e >> 6, c = e & 63;
    s_fr[c*65 + o] = fusw[o*128 + 64 + c];
  }
  if (tid < 64) {
    float a = b1b[tid] + 0.5f*b1w[tid*4+0] + 0.5f*b1w[tid*4+1]
            + in2*b1w[tid*4+2] + in3*b1w[tid*4+3];
    hid[tid] = fmaxf(a, 0.f);
  }
  __syncthreads();
  if (tid < 64) {
    float a = b2b[tid];
    #pragma unroll 8
    for (int k = 0; k < 64; k++) a = fmaf(b2w[tid*64+k], hid[k], a);
    emb[tid] = fmaxf(a, 0.f);
  }
  __syncthreads();
  if (tid < 4) {
    float a = rb[tid];
    for (int k = 0; k < 64; k++) a = fmaf(rw[tid*64+k], emb[k], a);
    r[tid] = 1.f / (1.f + expf(-a));
  } else if (tid < 6) {
    int t = tid - 4; float a = ob[t];
    for (int k = 0; k < 64; k++) a = fmaf(ow[t*64+k], emb[k], a);
    g_off[ci][t] = a;
  } else if (tid < 8) {
    int t = tid - 6; float a = sob[t];
    for (int k = 0; k < 64; k++) a = fmaf(sow[t*64+k], emb[k], a);
    g_stoff[ci][t] = a;
  }
  __syncthreads();
  for (int e = tid; e < 512; e += 256) {
    float a = 0.f, bsum = 0.f;
    #pragma unroll
    for (int ex = 0; ex < 4; ex++) {
      a    = fmaf(r[ex], wc[ex*512+e], a);
      bsum = fmaf(r[ex], we[ex*512+e], bsum);
    }
    g_wcpx[ci][e] = a;
    s_we2[e] = bsum;
  }
  __syncthreads();
  // M[j][o] = sum_c fusR[o][c] * we_px[c][j]
  for (int e = tid; e < 512; e += 256) {
    int j = e >> 6, o = e & 63;
    float a = 0.f;
    #pragma unroll 8
    for (int c = 0; c < 64; c++) a = fmaf(s_fr[c*65 + o], s_we2[c*8 + j], a);
    g_M[ci][j*64 + o] = a;
  }
}

// ---------------------------------------------------------------------------
// K2X: transpose x [b][64][9216] -> g_X [b][9216][64]  (channel-last)
// ---------------------------------------------------------------------------
__global__ __launch_bounds__(256) void k2x_transpose(const float* __restrict__ x) {
  __shared__ float tile[32][33];
  const int b = blockIdx.z, c0 = blockIdx.y*32, px0 = blockIdx.x*32;
  const int tx = threadIdx.x & 31, ty = threadIdx.x >> 5;
  #pragma unroll
  for (int i = 0; i < 4; i++)
    tile[ty + i*8][tx] = x[((size_t)(b*CC + c0 + ty + i*8))*NPX + px0 + tx];
  __syncthreads();
  #pragma unroll
  for (int i = 0; i < 4; i++) {
    int pxl = ty + i*8;
    g_X[((size_t)b*NPX + px0 + pxl)*CC + c0 + tx] = tile[tx][pxl];
  }
}

// ---------------------------------------------------------------------------
// K2 (mma.sync tf32, 3x-split): fused kernel_warp GEMM + 25-tap sta conv.
// ---------------------------------------------------------------------------
#define K2_SMEM_FLOATS (8192 + 4224 + 13824 + 1600)

__global__ __launch_bounds__(256, 2) void k2_sta_mma(const float* __restrict__ x,
                                                     const float* __restrict__ st,
                                                     const float* __restrict__ kcb) {
  extern __shared__ float sm[];
  float* s_b  = sm;                // [2][4096] hi, lo
  float* s_a  = sm + 8192;         // [k 64][px 64 pad66]
  float* s_x  = sm + 12416;        // [c 64][row 6][col 36]
  float* s_kb = sm + 26240;        // [1600]

  const int b = blockIdx.z, h0 = blockIdx.y*2, w0 = blockIdx.x*32;
  const int tid = threadIdx.x, wid = tid >> 5, l = tid & 31;
  const int g = l >> 2, tg = l & 3;
  const int mt = wid & 3, nth = wid >> 2;

  for (int e = tid; e < 4096; e += 256) {
    int k = e >> 6, px = e & 63;
    s_a[k*66 + px] = st[((b*CC + k)*HIN + h0 + (px >> 5))*WIN + w0 + (px & 31)];
  }
  for (int e = tid; e < 64*6*36; e += 256) {
    int col = e % 36; int row = (e / 36) % 6; int c = e / 216;
    int gy = min(max(h0 - 2 + row, 0), HIN - 1);
    int gx = min(max(w0 - 2 + col, 0), WIN - 1);
    s_x[e] = x[((b*CC + c)*HIN + gy)*WIN + gx];
  }
  for (int e = tid; e < 1600; e += 256) s_kb[e] = kcb[e];
  __syncthreads();

  uint32_t ah[8][4], al[8][4];
  {
    const int px0 = mt*16 + g, px1 = px0 + 8;
    #pragma unroll
    for (int ks = 0; ks < 8; ks++) {
      int r0 = (ks*8 + tg)*66, r1 = r0 + 4*66;
      float v0 = s_a[r0 + px0], v1 = s_a[r0 + px1];
      float v2 = s_a[r1 + px0], v3 = s_a[r1 + px1];
      ah[ks][0] = to_tf32(v0); al[ks][0] = to_tf32(v0 - __uint_as_float(ah[ks][0]));
      ah[ks][1] = to_tf32(v1); al[ks][1] = to_tf32(v1 - __uint_as_float(ah[ks][1]));
      ah[ks][2] = to_tf32(v2); al[ks][2] = to_tf32(v2 - __uint_as_float(ah[ks][2]));
      ah[ks][3] = to_tf32(v3); al[ks][3] = to_tf32(v3 - __uint_as_float(ah[ks][3]));
    }
  }

  float sacc[16];
  #pragma unroll
  for (int i = 0; i < 16; i++) sacc[i] = 0.f;

  const uint32_t sb = smem_u32(s_b);
  const int prow = mt >> 1, pcol0 = (mt & 1)*16 + g;

  for (int t = 0; t < 25; t++) {
    {
      const float* srch = g_bhi + t*4096;
      const float* srcl = g_blo + t*4096;
      #pragma unroll
      for (int i = 0; i < 4; i++) {
        int j = tid + i*256;
        cp16(sb + (uint32_t)j*16u,           srch + j*4);
        cp16(sb + 16384u + (uint32_t)j*16u,  srcl + j*4);
      }
      CP_COMMIT(); CP_WAIT0();
      __syncthreads();
    }

    const int rr = t / 5, dw = t - rr*5;

    float d[4][4];
    #pragma unroll
    for (int n = 0; n < 4; n++) {
      int c0 = ((nth*4 + n)*8 + 2*tg)*25 + t;
      d[n][0] = s_kb[c0];      d[n][1] = s_kb[c0 + 25];
      d[n][2] = d[n][0];       d[n][3] = d[n][1];
    }

    #pragma unroll
    for (int ks = 0; ks < 8; ks++) {
      #pragma unroll
      for (int n = 0; n < 4; n++) {
        int bo = ((nth*4 + n)*8 + ks)*64 + l*2;
        float2 bh = *(const float2*)&s_b[bo];
        float2 bl = *(const float2*)&s_b[4096 + bo];
        uint32_t bh0 = __float_as_uint(bh.x), bh1 = __float_as_uint(bh.y);
        uint32_t bl0 = __float_as_uint(bl.x), bl1 = __float_as_uint(bl.y);
        MMA_TF32(d[n], ah[ks], bh0, bh1);
        MMA_TF32(d[n], ah[ks], bl0, bl1);
        MMA_TF32(d[n], al[ks], bh0, bh1);
      }
    }

    #pragma unroll
    for (int n = 0; n < 4; n++) {
      int cb = (nth*4 + n)*8 + 2*tg;
      #pragma unroll
      for (int j = 0; j < 4; j++) {
        int c  = cb + (j & 1);
        int px = pcol0 + (j >> 1)*8;
        float gv = d[n][j];
        float lv = fmaf(0.45f, fabsf(gv), 0.55f*gv);
        float xv = s_x[c*216 + (prow + rr)*36 + px + dw];
        sacc[n*4 + j] = fmaf(lv, xv, sacc[n*4 + j]);
      }
    }
    __syncthreads();
  }

  #pragma unroll
  for (int n = 0; n < 4; n++) {
    int cb = (nth*4 + n)*8 + 2*tg;
    #pragma unroll
    for (int j = 0; j < 4; j++) {
      int c  = cb + (j & 1);
      int px = pcol0 + (j >> 1)*8;
      g_sta[((b*CC + c)*HIN + h0 + prow)*WIN + w0 + px] = sacc[n*4 + j];
    }
  }
}

// ---------------------------------------------------------------------------
// K2B: LR GEMMs  A = fusL @ sta,  B = fusR @ x, output channel-last.
// grid (72 pxblk, b, mat), 256 thr; per block 64o x 128px, K=64.
// ---------------------------------------------------------------------------
#define K2B_SMEM_FLOATS (8192 + 64*68)

__global__ __launch_bounds__(256, 4) void k2b_gemm(const float* __restrict__ x,
                                                   const float* __restrict__ fusw) {
  extern __shared__ float sm[];
  float* s_src = sm;           // [k 64][px 128]
  float* s_wT  = sm + 8192;    // [k 64][o 64 pad68]

  const int px0 = blockIdx.x*128, b = blockIdx.y, mat = blockIdx.z;
  const int tid = threadIdx.x;
  const float* src = mat ? (x + (size_t)b*CC*NPX) : (g_sta + (size_t)b*CC*NPX);
  const int mo = mat ? 64 : 0;
  float* dst = (mat ? g_B : g_A) + (size_t)b*NPX*CC;

  for (int e = tid; e < 8192; e += 256) {
    int k = e >> 7, p = e & 127;
    s_src[e] = src[(size_t)k*NPX + px0 + p];
  }
  for (int e = tid; e < 4096; e += 256) {
    int o = e >> 6, k = e & 63;
    s_wT[k*68 + o] = fusw[o*128 + mo + k];
  }
  __syncthreads();

  const int o0 = (tid & 15)*4, p0 = (tid >> 4)*8;
  float4 acc[8];
  #pragma unroll
  for (int i = 0; i < 8; i++) acc[i] = make_float4(0.f, 0.f, 0.f, 0.f);

  #pragma unroll 4
  for (int k = 0; k < 64; k++) {
    float4 w4 = *(const float4*)&s_wT[k*68 + o0];
    const float* sr = s_src + k*128 + p0;
    #pragma unroll
    for (int pp = 0; pp < 8; pp++) {
      float s = sr[pp];
      acc[pp].x = fmaf(w4.x, s, acc[pp].x);
      acc[pp].y = fmaf(w4.y, s, acc[pp].y);
      acc[pp].z = fmaf(w4.z, s, acc[pp].z);
      acc[pp].w = fmaf(w4.w, s, acc[pp].w);
    }
  }
  #pragma unroll
  for (int pp = 0; pp < 8; pp++)
    *(float4*)&dst[(size_t)(px0 + p0 + pp)*CC + o0] = acc[pp];
}

// ---------------------------------------------------------------------------
// K3 v3: out = bilin_stoff(A) + bilin_off(B) + M_par @ (wc_par @ bilin_off(X)) + fus_b
// Block: (b, Y, 64 px), 256 thr.
// ---------------------------------------------------------------------------
__global__ __launch_bounds__(256, 4) void k3_fuse(const float* __restrict__ fusb,
                                                  float* __restrict__ out) {
  __shared__ float  s_fea[4096];   // [c][64px]
  __shared__ float  s_t[512];      // [j][64px]
  __shared__ float  s_wc[1024];    // [pw][o*64+c]
  __shared__ float  s_M[1024];     // [pw][j*64+o]
  __shared__ float  s_fb[64];
  __shared__ int2   s_gi[128];     // [img][px]  row offsets (r*96+cb)
  __shared__ float4 s_gw[128];     // (wxa, wxb, wy0, wy1)

  const int b = blockIdx.z, Y = blockIdx.y, X0 = blockIdx.x * 64;
  const int tid = threadIdx.x;
  const int ph = Y & 1;

  for (int e = tid; e < 1024; e += 256) {
    int pw = e >> 9, i = e & 511;
    s_wc[pw*512 + i] = g_wcpx[ph*2 + pw][i];
    s_M[pw*512 + i]  = g_M[ph*2 + pw][i];
  }
  if (tid < 64) s_fb[tid] = fusb[tid];
  if (tid < 128) {
    int img = tid >> 6, px = tid & 63;
    int X = X0 + px; int ci = ph*2 + (X & 1);
    float offx = img ? g_stoff[ci][0] : g_off[ci][0];
    float offy = img ? g_stoff[ci][1] : g_off[ci][1];
    float pxf = (X + 0.5f)*0.5f - 0.5f + offx;
    float pyf = (Y + 0.5f)*0.5f - 0.5f + offy;
    float xf = floorf(pxf), yf = floorf(pyf);
    int ix0 = (int)xf, iy0 = (int)yf;
    float fx = pxf - xf, fy = pyf - yf;
    int cb = min(max(ix0, 0), WIN - 2);
    float wxa = 0.f, wxb = 0.f;
    if (ix0 >= 0 && ix0 <= WIN - 2)      { wxa = 1.f - fx; wxb = fx; }
    else if (ix0 == -1)                  { wxa = fx; }
    else if (ix0 == WIN - 1)             { wxb = 1.f - fx; }
    int ry0 = min(max(iy0, 0), HIN - 1), ry1 = min(max(iy0 + 1, 0), HIN - 1);
    float wy0 = (iy0 >= 0 && iy0 <= HIN - 1) ? (1.f - fy) : 0.f;
    float wy1 = (iy0 + 1 >= 0 && iy0 + 1 <= HIN - 1) ? fy : 0.f;
    s_gi[tid] = make_int2(ry0*WIN + cb, ry1*WIN + cb);
    s_gw[tid] = make_float4(wxa, wxb, wy0, wy1);
  }
  __syncthreads();

  // P1: fea0 = bilin_off(X)  (float4 over channels)
  {
    const float4* P = (const float4*)g_X + (size_t)b*NPX*16;
    for (int u = tid; u < 1024; u += 256) {
      int px = u & 63, c4 = u >> 6;
      int2 gi = s_gi[px];
      float4 w = s_gw[px];
      float4 a0 = __ldg(P + gi.x*16 + c4);
      float4 a1 = __ldg(P + gi.x*16 + 16 + c4);
      float4 b0 = __ldg(P + gi.y*16 + c4);
      float4 b1 = __ldg(P + gi.y*16 + 16 + c4);
      float4 v;
      v.x = w.z*(w.x*a0.x + w.y*a1.x) + w.w*(w.x*b0.x + w.y*b1.x);
      v.y = w.z*(w.x*a0.y + w.y*a1.y) + w.w*(w.x*b0.y + w.y*b1.y);
      v.z = w.z*(w.x*a0.z + w.y*a1.z) + w.w*(w.x*b0.z + w.y*b1.z);
      v.w = w.z*(w.x*a0.w + w.y*a1.w) + w.w*(w.x*b0.w + w.y*b1.w);
      int c = c4*4;
      s_fea[c*64 + px]     = v.x;
      s_fea[(c+1)*64 + px] = v.y;
      s_fea[(c+2)*64 + px] = v.z;
      s_fea[(c+3)*64 + px] = v.w;
    }
  }
  __syncthreads();

  // P2: t[j][px] = wc_par . fea0
  for (int e = tid; e < 512; e += 256) {
    int j = e >> 6, px = e & 63, pw = px & 1;
    const float* wr = s_wc + pw*512 + j*64;
    float a = 0.f;
    #pragma unroll 8
    for (int c = 0; c < 64; c++) a = fmaf(wr[c], s_fea[c*64 + px], a);
    s_t[j*64 + px] = a;
  }
  __syncthreads();

  // P3: out = bilinA + bilinB + M.t + bias
  {
    const float4* PA = (const float4*)g_A + (size_t)b*NPX*16;
    const float4* PB = (const float4*)g_B + (size_t)b*NPX*16;
    for (int u = tid; u < 1024; u += 256) {
      int px = u & 63, o4 = u >> 6, pw = px & 1;
      int2 gi1 = s_gi[64 + px]; float4 w1 = s_gw[64 + px];
      float4 A00 = __ldg(PA + gi1.x*16 + o4);
      float4 A01 = __ldg(PA + gi1.x*16 + 16 + o4);
      float4 A10 = __ldg(PA + gi1.y*16 + o4);
      float4 A11 = __ldg(PA + gi1.y*16 + 16 + o4);
      int2 gi0 = s_gi[px]; float4 w0 = s_gw[px];
      float4 B00 = __ldg(PB + gi0.x*16 + o4);
      float4 B01 = __ldg(PB + gi0.x*16 + 16 + o4);
      float4 B10 = __ldg(PB + gi0.y*16 + o4);
      float4 B11 = __ldg(PB + gi0.y*16 + 16 + o4);
      float4 r;
      r.x = w1.z*(w1.x*A00.x + w1.y*A01.x) + w1.w*(w1.x*A10.x + w1.y*A11.x)
          + w0.z*(w0.x*B00.x + w0.y*B01.x) + w0.w*(w0.x*B10.x + w0.y*B11.x);
      r.y = w1.z*(w1.x*A00.y + w1.y*A01.y) + w1.w*(w1.x*A10.y + w1.y*A11.y)
          + w0.z*(w0.x*B00.y + w0.y*B01.y) + w0.w*(w0.x*B10.y + w0.y*B11.y);
      r.z = w1.z*(w1.x*A00.z + w1.y*A01.z) + w1.w*(w1.x*A10.z + w1.y*A11.z)
          + w0.z*(w0.x*B00.z + w0.y*B01.z) + w0.w*(w0.x*B10.z + w0.y*B11.z);
      r.w = w1.z*(w1.x*A00.w + w1.y*A01.w) + w1.w*(w1.x*A10.w + w1.y*A11.w)
          + w0.z*(w0.x*B00.w + w0.y*B01.w) + w0.w*(w0.x*B10.w + w0.y*B11.w);
      int o0 = o4*4;
      r.x += s_fb[o0]; r.y += s_fb[o0+1]; r.z += s_fb[o0+2]; r.w += s_fb[o0+3];
      const float* Mp = s_M + pw*512;
      #pragma unroll
      for (int j = 0; j < 8; j++) {
        float tj = s_t[j*64 + px];
        float4 m4 = *(const float4*)&Mp[j*64 + o0];
        r.x = fmaf(m4.x, tj, r.x);
        r.y = fmaf(m4.y, tj, r.y);
        r.z = fmaf(m4.z, tj, r.z);
        r.w = fmaf(m4.w, tj, r.w);
      }
      float* op = out + ((size_t)(b*CC + o0)*HOUT + Y)*WOUT + X0 + px;
      op[0]            = r.x;
      op[HOUT*WOUT]    = r.y;
      op[2*HOUT*WOUT]  = r.z;
      op[3*HOUT*WOUT]  = r.w;
    }
  }
}

// ---------------------------------------------------------------------------
extern "C" void kernel_launch(void* const* d_in, const int* in_sizes, int n_in,
                              void* d_out, int out_size) {
  const float* x    = (const float*)d_in[0];
  const float* st   = (const float*)d_in[1];
  const float* kcw  = (const float*)d_in[2];
  const float* kcb  = (const float*)d_in[3];
  const float* wc   = (const float*)d_in[4];
  const float* we   = (const float*)d_in[5];
  const float* b1w  = (const float*)d_in[6];
  const float* b1b  = (const float*)d_in[7];
  const float* b2w  = (const float*)d_in[8];
  const float* b2b  = (const float*)d_in[9];
  const float* rw   = (const float*)d_in[10];
  const float* rb   = (const float*)d_in[11];
  const float* ow   = (const float*)d_in[12];
  const float* ob   = (const float*)d_in[13];
  const float* sow  = (const float*)d_in[14];
  const float* sob  = (const float*)d_in[15];
  const float* fusw = (const float*)d_in[16];
  const float* fusb = (const float*)d_in[17];
  float* out = (float*)d_out;

  const int smem2 = K2_SMEM_FLOATS * 4;
  const int smemb = K2B_SMEM_FLOATS * 4;
  cudaFuncSetAttribute(k2_sta_mma, cudaFuncAttributeMaxDynamicSharedMemorySize, smem2);
  cudaFuncSetAttribute(k2b_gemm,   cudaFuncAttributeMaxDynamicSharedMemorySize, smemb);

  k01_prep<<<204, 256>>>(kcw, b1w, b1b, b2w, b2b, rw, rb, ow, ob, sow, sob, wc, we, fusw);
  k2x_transpose<<<dim3(NPX/32, 2, BB), 256>>>(x);
  k2_sta_mma<<<dim3(WIN/32, HIN/2, BB), 256, smem2>>>(x, st, kcb);
  k2b_gemm<<<dim3(NPX/128, BB, 2), 256, smemb>>>(x, fusw);
  k3_fuse<<<dim3(WOUT/64, HOUT, BB), 256>>>(fusb, out);
}